// round 11
// baseline (speedup 1.0000x reference)
#include <cuda_runtime.h>
#include <math.h>

// SBEceLoss: logits [N,100] f32, labels [N] i64 -> scalar ece (f32)
// Thread-per-quarter-row with cp.async SMEM staging.
//   - 32-row tiles (12.8KB) double-buffered via cp.async.cg (16B, coalesced)
//   - inner scan: LDS + FSETP + FSEL + SEL per element (no counters)
//   - certification via merge intermediates: min(pairmax01, pairmax23) > -4
//     && -16 < m < 8  ->  acc == 0 proven exactly (fallback otherwise)
//   - per-block shared histogram -> global REDs
//   - last block computes 100x15 bin softmax + ECE, resets device state.

#define C_CLASSES 100
#define NB 15
#define TILE_ROWS 32
#define TILE_FLOATS (TILE_ROWS * C_CLASSES)   // 3200
#define TILE_BYTES  (TILE_FLOATS * 4)         // 12800 (tiles are 128B-aligned)
#define THREADS 128
#define FULLM 0xffffffffu

__device__ int g_cnt[C_CLASSES];
__device__ int g_acc[C_CLASSES];
__device__ unsigned g_done;

__device__ __forceinline__ void cp_async16(unsigned saddr, const void* gaddr) {
    asm volatile("cp.async.cg.shared.global [%0], [%1], 16;" :: "r"(saddr), "l"(gaddr));
}
__device__ __forceinline__ void cp_commit() {
    asm volatile("cp.async.commit_group;" ::: "memory");
}

__global__ void __launch_bounds__(THREADS)
fused_kernel(const float* __restrict__ logits,
             const long long* __restrict__ labels,
             int n_rows, float* __restrict__ out) {
    __shared__ __align__(16) float sbuf[2][TILE_FLOATS];   // 25.6 KB
    __shared__ int  s_cnt[C_CLASSES];
    __shared__ int  s_acc[C_CLASSES];
    __shared__ bool s_last;

    const int tid = threadIdx.x;
    for (int i = tid; i < C_CLASSES; i += THREADS) { s_cnt[i] = 0; s_acc[i] = 0; }

    const int tiles = (n_rows + TILE_ROWS - 1) / TILE_ROWS;
    const unsigned sb[2] = {
        (unsigned)__cvta_generic_to_shared(&sbuf[0][0]),
        (unsigned)__cvta_generic_to_shared(&sbuf[1][0])
    };

    // ---- prologue prefetch (tile = blockIdx.x into buffer 0) ----
    int tile = blockIdx.x;
    if (tile < tiles) {
        const char* g = (const char*)logits + (size_t)tile * TILE_BYTES;
        int valid = min(TILE_ROWS, n_rows - tile * TILE_ROWS) * 400;
        #pragma unroll
        for (int k = 0; k < 7; k++) {
            int off = (tid + k * THREADS) * 16;
            if (off < TILE_BYTES && off < valid) cp_async16(sb[0] + off, g + off);
        }
    }
    cp_commit();

    const int q = tid & 3;               // quarter within the row
    int b = 0;
    for (; tile < tiles; tile += gridDim.x, b ^= 1) {
        // issue next tile into the other buffer (overlaps current processing)
        int next = tile + gridDim.x;
        if (next < tiles) {
            const char* g = (const char*)logits + (size_t)next * TILE_BYTES;
            int valid = min(TILE_ROWS, n_rows - next * TILE_ROWS) * 400;
            unsigned sdst = sb[b ^ 1];
            #pragma unroll
            for (int k = 0; k < 7; k++) {
                int off = (tid + k * THREADS) * 16;
                if (off < TILE_BYTES && off < valid) cp_async16(sdst + off, g + off);
            }
        }
        cp_commit();
        asm volatile("cp.async.wait_group 1;" ::: "memory");  // current tile ready
        __syncthreads();

        // ---- thread-local quarter-row scan (4 issues/elem, conflict-free) ----
        const float* rp = &sbuf[b][tid * 25];
        float m   = rp[0];
        int   idx = q * 25;
        #pragma unroll
        for (int i = 1; i < 25; i++) {
            float x = rp[i];
            bool p = x > m;                  // strict > keeps first occurrence
            m   = p ? x : m;
            idx = p ? q * 25 + i : idx;
        }

        // ---- merge 4 quarters: (value desc, index asc) + cert lower bound ----
        // round 1 (off=1): lanes now hold pair maxes (q01 and q23)
        {
            float om = __shfl_xor_sync(FULLM, m,   1);
            int   oi = __shfl_xor_sync(FULLM, idx, 1);
            bool take = (om > m) || (om == m && oi < idx);
            m   = take ? om : m;
            idx = take ? oi : idx;
        }
        float second_lb;
        // round 2 (off=2): min of the two pair maxes = a REAL element distinct
        // from the argmax element -> lower bound on the row's second max.
        {
            float om = __shfl_xor_sync(FULLM, m,   2);
            int   oi = __shfl_xor_sync(FULLM, idx, 2);
            second_lb = fminf(m, om);
            bool take = (om > m) || (om == m && oi < idx);
            m   = take ? om : m;
            idx = take ? oi : idx;
        }

        int row = tile * TILE_ROWS + (tid >> 2);
        if (q == 0 && row < n_rows) {
            // cert: second element > -4 > m-12 (m < 8) and |m| < 16 =>
            // log(sumexp) >= log(1+e^-12) = 6.1e-6 > ulp(16)/2 => max logprob
            // strictly < 0 => never equals an integer label => acc = 0.
            bool good = (second_lb > -4.0f) && (m < 8.0f) && (m > -16.0f);
            if (!good) {   // statistically never taken
                const float* rb = &sbuf[b][(tid >> 2) * C_CLASSES];
                float sv = 0.0f;
                for (int i = 0; i < C_CLASSES; i++) sv += expf(rb[i] - m);
                float pred = m - (m + logf(sv));
                if (pred == (float)labels[row]) atomicAdd(&s_acc[idx], 1);
            }
            atomicAdd(&s_cnt[idx], 1);
        }
        __syncthreads();   // all reads of buf b done before it is re-filled
    }
    asm volatile("cp.async.wait_group 0;" ::: "memory");

    // ---- flush block histogram to global ----
    __syncthreads();
    for (int i = tid; i < C_CLASSES; i += THREADS) {
        int c = s_cnt[i]; if (c) atomicAdd(&g_cnt[i], c);
        int a = s_acc[i]; if (a) atomicAdd(&g_acc[i], a);
    }
    __threadfence();
    __syncthreads();

    if (tid == 0) {
        unsigned rank = atomicAdd(&g_done, 1u);
        s_last = (rank == gridDim.x - 1);
    }
    __syncthreads();
    if (!s_last) return;

    // ================= finalize (last block only; alias tile SMEM) =========
    float (*s_coef)[NB + 1] = reinterpret_cast<float(*)[NB + 1]>(&sbuf[0][0]); // 1600 f
    int*   s_c2   = reinterpret_cast<int*>(&sbuf[0][1600]);
    int*   s_a2   = reinterpret_cast<int*>(&sbuf[0][1728]);
    float* s_sum  = &sbuf[0][1856];
    float* s_conf = &sbuf[0][1872];
    float* s_accs = &sbuf[0][1888];

    int t = tid;
    if (t < C_CLASSES) {
        int cnt = __ldcg(&g_cnt[t]);
        int ac  = __ldcg(&g_acc[t]);
        s_c2[t] = cnt;
        s_a2[t] = ac;
        float cf = (float)t;
        float d[NB];
        float dmax = __int_as_float(0xff800000);
        #pragma unroll
        for (int jj = 0; jj < NB; jj++) {
            float aj = (float)((2 * jj + 1) / 30.0);
            float tt = cf - aj;
            d[jj] = -(tt * tt) / 0.01f;
            dmax = fmaxf(dmax, d[jj]);
        }
        float denom = 0.0f;
        #pragma unroll
        for (int jj = 0; jj < NB; jj++) denom += expf(d[jj] - dmax);
        #pragma unroll
        for (int jj = 0; jj < NB; jj++) s_coef[t][jj] = expf(d[jj] - dmax) / denom;
        g_cnt[t] = 0;     // reset for next graph replay
        g_acc[t] = 0;
    }
    if (t == 0) g_done = 0;
    __syncthreads();

    if (t < NB) {
        float sum_c = 0.0f, sum_cc = 0.0f, sum_a = 0.0f;
        for (int c = 0; c < C_CLASSES; c++) {
            int cnt = s_c2[c];
            int ac  = s_a2[c];
            if ((cnt | ac) == 0) continue;
            float coeff = s_coef[c][t];
            float fcnt  = (float)cnt;   // exact: cnt < 2^24
            float cf    = (float)c;
            sum_c  += fcnt * coeff;
            sum_cc += fcnt * cf * coeff;
            sum_a  += (float)ac * coeff;
        }
        s_sum[t]  = sum_c;
        s_conf[t] = sum_cc;
        s_accs[t] = sum_a;
    }
    __syncthreads();

    if (t == 0) {
        float tot = 0.0f;
        #pragma unroll
        for (int jj = 0; jj < NB; jj++) tot += fabsf(s_sum[jj]);
        float wden = fmaxf(tot, 1e-5f);
        float acc2 = 0.0f;
        #pragma unroll
        for (int jj = 0; jj < NB; jj++) {
            float den = fmaxf(s_sum[jj], 1e-5f);
            float bc  = s_conf[jj] / den;
            float ba  = s_accs[jj] / den;
            float w   = s_sum[jj] / wden;
            float df  = bc - ba;
            acc2 += df * df * w;
        }
        out[0] = sqrtf(acc2);
    }
}

extern "C" void kernel_launch(void* const* d_in, const int* in_sizes, int n_in,
                              void* d_out, int out_size) {
    const float*     logits = (const float*)d_in[0];
    const long long* labels = (const long long*)d_in[1];
    float*           out    = (float*)d_out;
    int n_rows = in_sizes[1];  // labels count = N

    // 16384 tiles / 1024 blocks = 16 tiles each, exact; 8 blocks/SM resident
    fused_kernel<<<1024, THREADS>>>(logits, labels, n_rows, out);
}